// round 16
// baseline (speedup 1.0000x reference)
#include <cuda_runtime.h>
#include <cuda_fp16.h>
#include <cstdint>

// ---------------- problem constants ----------------
#define B_    4
#define CIN   256
#define H_    56
#define W_    56
#define HW    3136
#define OUT_  256
#define WS_   32
#define K2    49
#define KP    52
#define MPROJ 288
#define PC_   272
#define PH    62
#define PW    64

// attn dynamic smem layout (bytes) — R11 winner
#define ATT_U0     0
#define ATT_SLOG   26624
#define ATT_SX2    58624
#define ATT_CW1H   65792
#define ATT_CW2H   66304
#define ATT_SX1    67328
#define ATT_SCB    67840
#define ATT_S2S    67968
#define ATT_T2S    68032
#define ATT_SINV   68096
#define ATT_SMEM   69120

// ---------------- scratch (device globals) --------------------------------
__device__ float  g_bc[MPROJ];
__device__ float  g_s1[16], g_t1[16];
__device__ __align__(16) __half g_cw1h[256];
__device__ __align__(16) __half g_cw2h[512];
__device__ __align__(16) __half g_wch_b[MPROJ * CIN];
__device__ __align__(16) __half g_wch_s[MPROJ * CIN];
__device__ __align__(16) __half g_xtb[(size_t)B_ * HW * CIN];
__device__ __align__(16) __half g_xts[(size_t)B_ * HW * CIN];
__device__ float  g_proj[B_ * MPROJ * HW];
__device__ float  g_pad[(size_t)B_ * PC_ * PH * PW];
__device__ __half g_w[(size_t)B_ * WS_ * HW * KP];
__device__ float  g_agg[B_ * OUT_ * HW];

__device__ __forceinline__ int refl(int i, int n) {
    if (i < 0) i = -i;
    if (i >= n) i = 2 * n - 2 - i;
    return i;
}

__device__ __forceinline__ void mma16816(float (&d)[4], const unsigned (&a)[4],
                                         const unsigned (&b)[2], const float (&c)[4]) {
    asm volatile(
        "mma.sync.aligned.m16n8k16.row.col.f32.f16.f16.f32 "
        "{%0,%1,%2,%3}, {%4,%5,%6,%7}, {%8,%9}, {%10,%11,%12,%13};\n"
        : "=f"(d[0]), "=f"(d[1]), "=f"(d[2]), "=f"(d[3])
        : "r"(a[0]), "r"(a[1]), "r"(a[2]), "r"(a[3]),
          "r"(b[0]), "r"(b[1]),
          "f"(c[0]), "f"(c[1]), "f"(c[2]), "f"(c[3]));
}

__device__ __forceinline__ void ldmatrix_x4(unsigned (&r)[4], uint32_t addr) {
    asm volatile("ldmatrix.sync.aligned.m8n8.x4.shared.b16 {%0,%1,%2,%3}, [%4];\n"
                 : "=r"(r[0]), "=r"(r[1]), "=r"(r[2]), "=r"(r[3]) : "r"(addr));
}

__device__ __forceinline__ void ldmatrix_x2(unsigned (&r)[2], uint32_t addr) {
    asm volatile("ldmatrix.sync.aligned.m8n8.x2.shared.b16 {%0,%1}, [%2];\n"
                 : "=r"(r[0]), "=r"(r[1]) : "r"(addr));
}

// ---------------- kernel 0: pack weights + bn1 fold + fp16 splits ---------
__global__ void pack_kernel(const float* __restrict__ w1, const float* __restrict__ b1,
                            const float* __restrict__ w2, const float* __restrict__ b2,
                            const float* __restrict__ w3, const float* __restrict__ b3,
                            const float* __restrict__ bn1g, const float* __restrict__ bn1b,
                            const float* __restrict__ bn1m, const float* __restrict__ bn1v,
                            const float* __restrict__ cw1, const float* __restrict__ cw2) {
    int i = blockIdx.x * blockDim.x + threadIdx.x;
    if (i < MPROJ * CIN) {
        int r = i / CIN, c = i % CIN;
        float v;
        if (r < 16)      v = w1[r * CIN + c];
        else if (r < 32) v = w2[(r - 16) * CIN + c];
        else             v = w3[(r - 32) * CIN + c];
        __half hb = __float2half(v);
        g_wch_b[i] = hb;
        g_wch_s[i] = __float2half(v - __half2float(hb));
    }
    if (i < MPROJ) {
        g_bc[i] = (i < 16) ? b1[i] : ((i < 32) ? b2[i - 16] : b3[i - 32]);
    }
    if (i < 16) {
        float s = bn1g[i] * rsqrtf(bn1v[i] + 1e-5f);
        g_s1[i] = s;
        g_t1[i] = bn1b[i] - s * bn1m[i];
    }
    if (i < 256) g_cw1h[i] = __float2half(cw1[i]);
    if (i < 512) g_cw2h[i] = __float2half(cw2[i]);
}

// ---------------- kernel 0b: transpose + fp16-split X ---------------------
__global__ __launch_bounds__(256) void prep_x(const float* __restrict__ x) {
    __shared__ float tile[32][33];
    int p0 = blockIdx.x * 32, k0 = blockIdx.y * 32, b = blockIdx.z;
    int t = threadIdx.x;
    for (int i = t; i < 1024; i += 256) {
        int kk = i >> 5, pp = i & 31;
        tile[kk][pp] = x[((size_t)(b * CIN + k0 + kk)) * HW + p0 + pp];
    }
    __syncthreads();
    for (int i = t; i < 1024; i += 256) {
        int pp = i >> 5, kk = i & 31;
        float v = tile[kk][pp];
        __half hb = __float2half(v);
        size_t o = ((size_t)(b * HW + p0 + pp)) * CIN + k0 + kk;
        g_xtb[o] = hb;
        g_xts[o] = __float2half(v - __half2float(hb));
    }
}

// ---------------- kernel 1: projection GEMM via 3-term fp16 HMMA ----------
__global__ __launch_bounds__(256) void proj_gemm() {
    __shared__ __align__(16) __half Xb[64 * 72], Xs[64 * 72];
    __shared__ __align__(16) __half Wb[96 * 72], Ws[96 * 72];

    int b  = blockIdx.z;
    int p0 = blockIdx.x * 64;
    int ch0 = blockIdx.y * 96;
    int t  = threadIdx.x;
    int warp = t >> 5, lane = t & 31;
    int mt = warp >> 1, nh = warp & 1;
    int qp = lane & 3, rp = lane >> 2;

    float acc[6][4];
#pragma unroll
    for (int j = 0; j < 6; j++)
#pragma unroll
        for (int c = 0; c < 4; c++) acc[j][c] = 0.0f;

    uint32_t xb_base = (uint32_t)__cvta_generic_to_shared(Xb);
    uint32_t xs_base = (uint32_t)__cvta_generic_to_shared(Xs);
    uint32_t wb_base = (uint32_t)__cvta_generic_to_shared(Wb);
    uint32_t ws_base = (uint32_t)__cvta_generic_to_shared(Ws);
    uint32_t a_off = (uint32_t)(mt * 16 + (lane & 15)) * 144u + (uint32_t)(lane >> 4) * 16u;
    int ln = lane & 15;
    uint32_t b_lane_off = (uint32_t)(ln & 7) * 144u + ((ln & 8) ? 16u : 0u);

    const uint4* gxb4 = reinterpret_cast<const uint4*>(g_xtb);
    const uint4* gxs4 = reinterpret_cast<const uint4*>(g_xts);
    const uint4* gwb4 = reinterpret_cast<const uint4*>(g_wch_b);
    const uint4* gws4 = reinterpret_cast<const uint4*>(g_wch_s);

    for (int k0 = 0; k0 < CIN; k0 += 64) {
        int kq = k0 >> 3;
        for (int i = t; i < 512; i += 256) {
            int r = i >> 3, c = i & 7;
            size_t src = (size_t)(b * HW + p0 + r) * 32 + kq + c;
            reinterpret_cast<uint4*>(Xb)[r * 9 + c] = gxb4[src];
            reinterpret_cast<uint4*>(Xs)[r * 9 + c] = gxs4[src];
        }
        for (int i = t; i < 768; i += 256) {
            int r = i >> 3, c = i & 7;
            size_t src = (size_t)(ch0 + r) * 32 + kq + c;
            reinterpret_cast<uint4*>(Wb)[r * 9 + c] = gwb4[src];
            reinterpret_cast<uint4*>(Ws)[r * 9 + c] = gws4[src];
        }
        __syncthreads();

#pragma unroll
        for (int kk = 0; kk < 4; kk++) {
            unsigned axb[4], axs[4];
            ldmatrix_x4(axb, xb_base + a_off + (uint32_t)kk * 32u);
            ldmatrix_x4(axs, xs_base + a_off + (uint32_t)kk * 32u);
#pragma unroll
            for (int j = 0; j < 6; j++) {
                uint32_t boff = (uint32_t)((nh * 6 + j) * 1152) + b_lane_off
                              + (uint32_t)kk * 32u;
                unsigned bb[2], bs[2];
                ldmatrix_x2(bb, wb_base + boff);
                ldmatrix_x2(bs, ws_base + boff);
                mma16816(acc[j], axb, bb, acc[j]);
                mma16816(acc[j], axs, bb, acc[j]);
                mma16816(acc[j], axb, bs, acc[j]);
            }
        }
        __syncthreads();
    }

    int pxl = p0 + mt * 16 + rp;
#pragma unroll
    for (int j = 0; j < 6; j++) {
        int chg = ch0 + (nh * 6 + j) * 8 + 2 * qp;
        float b0 = g_bc[chg], b1 = g_bc[chg + 1];
        float v0 = acc[j][0] + b0, v1 = acc[j][1] + b1;
        float v2 = acc[j][2] + b0, v3 = acc[j][3] + b1;
        if (chg < 16)      { float s = g_s1[chg], tt = g_t1[chg];
                             v0 = fmaf(s, v0, tt); v2 = fmaf(s, v2, tt); }
        else if (chg < 32) { float s = g_s1[chg - 16]; v0 *= s; v2 *= s; }
        int ch1 = chg + 1;
        if (ch1 < 16)      { float s = g_s1[ch1], tt = g_t1[ch1];
                             v1 = fmaf(s, v1, tt); v3 = fmaf(s, v3, tt); }
        else if (ch1 < 32) { float s = g_s1[ch1 - 16]; v1 *= s; v3 *= s; }
        size_t r0 = (size_t)(b * MPROJ + chg) * HW;
        size_t r1 = (size_t)(b * MPROJ + ch1) * HW;
        g_proj[r0 + pxl]     = v0;
        g_proj[r1 + pxl]     = v1;
        g_proj[r0 + pxl + 8] = v2;
        g_proj[r1 + pxl + 8] = v3;
    }
}

// ---------------- kernel 1b: reflect-pad (batched loads, MLP=16) ----------
__global__ __launch_bounds__(256) void pad_kernel() {
    int c = blockIdx.x, b = blockIdx.y;
    const float* src = g_proj + ((size_t)(b * MPROJ + 16 + c)) * HW;
    float* dst = g_pad + ((size_t)(b * PC_ + c)) * PH * PW;
    int t = threadIdx.x;
    int col = t & 63;
    int r0 = t >> 6;
    int ox = refl(col - 3, W_);
    float v[16];
#pragma unroll
    for (int i = 0; i < 16; i++) {
        int r = r0 + i * 4;
        if (r < PH) {
            int oy = refl(r - 3, H_);
            v[i] = src[oy * W_ + ox];
        }
    }
#pragma unroll
    for (int i = 0; i < 16; i++) {
        int r = r0 + i * 4;
        if (r < PH) dst[r * PW + col] = v[i];
    }
}

// ---------------- kernel 2: attention weights + softmax (HMMA) ------------
__global__ __launch_bounds__(384, 3) void attn_kernel(
    const float* __restrict__ bn2g, const float* __restrict__ bn2b,
    const float* __restrict__ bn2m, const float* __restrict__ bn2v,
    const float* __restrict__ cb) {

    extern __shared__ __align__(16) char smem_raw[];
    __half* act0h = (__half*)(smem_raw + ATT_U0);
    __half* slog2 = (__half*)(smem_raw + ATT_U0);
    __half* slog  = (__half*)(smem_raw + ATT_SLOG);
    float*  sx2   = (float*)(smem_raw + ATT_SX2);
    __half* scw1h = (__half*)(smem_raw + ATT_CW1H);
    __half* scw2h = (__half*)(smem_raw + ATT_CW2H);
    float*  sx1   = (float*)(smem_raw + ATT_SX1);
    float*  scb   = (float*)(smem_raw + ATT_SCB);
    float*  s2s   = (float*)(smem_raw + ATT_S2S);
    float*  t2s   = (float*)(smem_raw + ATT_T2S);
    float*  sinv  = (float*)(smem_raw + ATT_SINV);

    int t = threadIdx.x;
    int b = blockIdx.y;
    int p0 = blockIdx.x * 8;
    int h = p0 / W_, w0 = p0 % W_;

    if (t < 32) {
        reinterpret_cast<uint4*>(scw1h)[t] = reinterpret_cast<const uint4*>(g_cw1h)[t];
    } else if (t < 96) {
        reinterpret_cast<uint4*>(scw2h)[t - 32] = reinterpret_cast<const uint4*>(g_cw2h)[t - 32];
    } else if (t < 128) {
        scb[t - 96] = cb[t - 96];
    } else if (t < 144) {
        int c = t - 128;
        float ss = bn2g[c] * rsqrtf(bn2v[c] + 1e-5f);
        s2s[c] = ss; t2s[c] = bn2b[c] - ss * bn2m[c];
    } else if (t < 272) {
        int idx = t - 144;
        int c = idx >> 3, pix = idx & 7;
        sx1[pix * 16 + c] = g_proj[((size_t)b * MPROJ + c) * HW + p0 + pix];
    }
    const float* padb = g_pad + (size_t)b * PC_ * PH * PW;
    for (int i = t; i < 448; i += 384) {
        int c = i / 28, rem = i - c * 28, dy = rem >> 2, cg = rem & 3;
        float4 v = *reinterpret_cast<const float4*>(
            padb + ((size_t)c * PH + h + dy) * PW + w0 + cg * 4);
        *reinterpret_cast<float4*>(sx2 + c * 112 + dy * 16 + cg * 4) = v;
    }
    __syncthreads();

    for (int pt = t; pt < 392; pt += 384) {
        int pix = pt & 7, k = pt >> 3;
        int dy = k / 7, dx = k - dy * 7;
        const float* x2p = sx2 + dy * 16 + dx + pix;
        const float* x1p = sx1 + pix * 16;
        __half2* dst = reinterpret_cast<__half2*>(act0h + pt * 24);
#pragma unroll
        for (int q = 0; q < 8; q++) {
            float a0 = fmaxf(x1p[2 * q]     - x2p[(2 * q) * 112],     0.0f);
            float a1 = fmaxf(x1p[2 * q + 1] - x2p[(2 * q + 1) * 112], 0.0f);
            dst[q] = __floats2half2_rn(a0, a1);
        }
    }
    __syncthreads();

    {
        int warp = t >> 5, lane = t & 31;
        int qp = lane & 3, rp = lane >> 2;
        int k0 = qp * 2;

        unsigned b1f[2][2], b2f[4][2];
#pragma unroll
        for (int j = 0; j < 2; j++) {
            int o = j * 8 + rp;
            b1f[j][0] = *reinterpret_cast<const unsigned*>(scw1h + o * 16 + k0);
            b1f[j][1] = *reinterpret_cast<const unsigned*>(scw1h + o * 16 + k0 + 8);
        }
#pragma unroll
        for (int j = 0; j < 4; j++) {
            int g = j * 8 + rp;
            b2f[j][0] = *reinterpret_cast<const unsigned*>(scw2h + g * 16 + k0);
            b2f[j][1] = *reinterpret_cast<const unsigned*>(scw2h + g * 16 + k0 + 8);
        }
        float s2v[4] = {s2s[k0], s2s[k0 + 1], s2s[k0 + 8], s2s[k0 + 9]};
        float t2v[4] = {t2s[k0], t2s[k0 + 1], t2s[k0 + 8], t2s[k0 + 9]};
        float cbv[4][2];
#pragma unroll
        for (int j = 0; j < 4; j++) {
            cbv[j][0] = scb[j * 8 + k0];
            cbv[j][1] = scb[j * 8 + k0 + 1];
        }

        uint32_t act_base = (uint32_t)__cvta_generic_to_shared(act0h);
        for (int tile = warp; tile < 25; tile += 12) {
            unsigned a1[4];
            uint32_t addr = act_base + (uint32_t)(tile * 16 + (lane & 15)) * 48u
                          + (uint32_t)(lane >> 4) * 16u;
            ldmatrix_x4(a1, addr);

            float z4[4] = {0.f, 0.f, 0.f, 0.f};
            float d0[4], d1[4];
            mma16816(d0, a1, b1f[0], z4);
            mma16816(d1, a1, b1f[1], z4);

            unsigned a2[4];
            {
                __half2 hv;
                hv = __floats2half2_rn(fmaxf(fmaf(s2v[0], d0[0], t2v[0]), 0.f),
                                       fmaxf(fmaf(s2v[1], d0[1], t2v[1]), 0.f));
                a2[0] = *reinterpret_cast<unsigned*>(&hv);
                hv = __floats2half2_rn(fmaxf(fmaf(s2v[0], d0[2], t2v[0]), 0.f),
                                       fmaxf(fmaf(s2v[1], d0[3], t2v[1]), 0.f));
                a2[1] = *reinterpret_cast<unsigned*>(&hv);
                hv = __floats2half2_rn(fmaxf(fmaf(s2v[2], d1[0], t2v[2]), 0.f),
                                       fmaxf(fmaf(s2v[3], d1[1], t2v[3]), 0.f));
                a2[2] = *reinterpret_cast<unsigned*>(&hv);
                hv = __floats2half2_rn(fmaxf(fmaf(s2v[2], d1[2], t2v[2]), 0.f),
                                       fmaxf(fmaf(s2v[3], d1[3], t2v[3]), 0.f));
                a2[3] = *reinterpret_cast<unsigned*>(&hv);
            }

            int r0 = tile * 16 + rp;
            bool hi_ok = (r0 + 8 < 392);
#pragma unroll
            for (int j = 0; j < 4; j++) {
                float c2[4] = {cbv[j][0], cbv[j][1], cbv[j][0], cbv[j][1]};
                mma16816(c2, a2, b2f[j], c2);
                int g0 = j * 8 + k0;
                *reinterpret_cast<__half2*>(slog + r0 * 40 + g0) =
                    __floats2half2_rn(c2[0], c2[1]);
                if (hi_ok)
                    *reinterpret_cast<__half2*>(slog + (r0 + 8) * 40 + g0) =
                        __floats2half2_rn(c2[2], c2[3]);
            }
        }
    }
    __syncthreads();

    // phase4: softmax, 2 groups per thread via half2 loads
    if (t < 128) {
        int pix = t >> 4, gp = t & 15;
        const __half2* src = reinterpret_cast<const __half2*>(slog) + pix * 20 + gp;
        float m0 = -1e30f, m1 = -1e30f;
#pragma unroll
        for (int k = 0; k < 49; k++) {
            float2 f = __half22float2(src[k * 160]);
            m0 = fmaxf(m0, f.x);
            m1 = fmaxf(m1, f.y);
        }
        int g0 = 2 * gp;
        __half* d0 = slog2 + (pix * 32 + g0) * 52;
        __half* d1 = d0 + 52;
        float s0 = 0.0f, s1 = 0.0f;
#pragma unroll
        for (int k = 0; k < 49; k++) {
            float2 f = __half22float2(src[k * 160]);
            float e0 = __expf(f.x - m0), e1 = __expf(f.y - m1);
            s0 += e0; s1 += e1;
            d0[k] = __float2half(e0);
            d1[k] = __float2half(e1);
        }
#pragma unroll
        for (int q = 49; q < 52; q++) { d0[q] = __float2half(0.0f); d1[q] = __float2half(0.0f); }
        sinv[pix * 32 + g0]     = 1.0f / s0;
        sinv[pix * 32 + g0 + 1] = 1.0f / s1;
    }
    __syncthreads();

    {
        __half2* gw2 = reinterpret_cast<__half2*>(g_w);
        const __half2* sl2 = reinterpret_cast<const __half2*>(slog2);
        int r = t / 26, k2 = t - r * 26;
        for (int i = t; i < 6656; i += 384) {
            int pix = r >> 5, g = r & 31;
            float2 f = __half22float2(sl2[r * 26 + k2]);
            float inv = sinv[r];
            gw2[(((size_t)(b * WS_ + g)) * HW + p0 + pix) * 26 + k2] =
                __floats2half2_rn(f.x * inv, f.y * inv);
            r += 14; k2 += 20;
            if (k2 >= 26) { k2 -= 26; r++; }
        }
    }
}

// ---------------- kernel 3: aggregation (R12 version) ---------------------
__global__ __launch_bounds__(128) void agg_kernel() {
    __shared__ __align__(4) __half swh[64 * KP];
    __shared__ __align__(16) float sx3[8 * 14 * 24];

    int b = blockIdx.z, g = blockIdx.y, tile = blockIdx.x;
    int ty0 = (tile / 7) * 8, tx0 = (tile % 7) * 8;
    int t = threadIdx.x;

    const __half2* gw2 = reinterpret_cast<const __half2*>(g_w);
    size_t wbase = ((size_t)(b * WS_ + g)) * HW;
    for (int i = t; i < 1664; i += 128) {
        int run = i / 208, off = i - run * 208;
        reinterpret_cast<__half2*>(swh)[run * 208 + off] =
            gw2[(wbase + (ty0 + run) * W_ + tx0) * 26 + off];
    }
    const float* padb = g_pad + ((size_t)(b * PC_) + 16 + g * 8) * PH * PW;
    for (int i = t; i < 448; i += 128) {
        int c = i / 56, rem = i - c * 56, r = rem >> 2, cg = rem & 3;
        float4 v = *reinterpret_cast<const float4*>(
            padb + ((size_t)c * PH + ty0 + r) * PW + tx0 + cg * 4);
        *reinterpret_cast<float4*>(sx3 + (c * 14 + r) * 24 + cg * 4) = v;
    }
    __syncthreads();

    int pl = t & 63, sq = t >> 6;
    int pr = pl >> 3, pc = pl & 7;
    const __half2* wp = reinterpret_cast<const __half2*>(swh + pl * KP);
    const float* xb = sx3 + sq * 4 * 336 + pr * 24 + pc;

    float a0 = 0.f, a1 = 0.f, a2 = 0.f, a3 = 0.f;
#pragma unroll
    for (int k2 = 0; k2 < 25; k2++) {
        float2 wf = __half22float2(wp[k2]);
        {
            int k = 2 * k2;
            int xo = (k / 7) * 24 + (k % 7);
            a0 = fmaf(xb[xo],        wf.x, a0);
            a1 = fmaf(xb[336 + xo],  wf.x, a1);
            a2 = fmaf(xb[672 + xo],  wf.x, a2);
            a3 = fmaf(xb[1008 + xo], wf.x, a3);
        }
        if (2 * k2 + 1 < 49) {
            int k = 2 * k2 + 1;
            int xo = (k / 7) * 24 + (k % 7);
            a0 = fmaf(xb[xo],        wf.y, a0);
            a1 = fmaf(xb[336 + xo],  wf.y, a1);
            a2 = fmaf(xb[672 + xo],  wf.y, a2);
            a3 = fmaf(xb[1008 + xo], wf.y, a3);
        }
    }
    int p = (ty0 + pr) * W_ + tx0 + pc;
    float* dst = g_agg + ((size_t)b * OUT_ + g * 8 + sq * 4) * HW + p;
    dst[0] = a0; dst[HW] = a1; dst[2 * HW] = a2; dst[3 * HW] = a3;
}

// ---------------- kernel 4: position2 grouped conv ------------------------
__global__ __launch_bounds__(128) void pos2_kernel(const float* __restrict__ pos2w,
                                                   float* __restrict__ out) {
    __shared__ __align__(16) float sw[64 * KP];
    __shared__ __align__(16) float spw[8 * 60];
    __shared__ float sxv[8 * 64];

    int b = blockIdx.z, g = blockIdx.y, p0 = blockIdx.x * 64;
    int t = threadIdx.x;

    const __half2* gw2 = reinterpret_cast<const __half2*>(g_w);
    size_t base2 = (((size_t)(b * WS_ + g)) * HW + p0) * 26;
    for (int i = t; i < 1664; i += 128) {
        float2 f = __half22float2(gw2[base2 + i]);
        *reinterpret_cast<float2*>(sw + 2 * i) = f;
    }
    for (int i = t; i < 480; i += 128) {
        int o = i / 60, q = i - o * 60;
        spw[i] = (q < 57) ? pos2w[(g * 8 + o) * 57 + q] : 0.0f;
    }
    for (int i = t; i < 512; i += 128) {
        int s = i >> 6, pl = i & 63;
        sxv[i] = g_agg[((size_t)b * OUT_ + s * 32 + g) * HW + p0 + pl];
    }
    __syncthreads();

    int pl = t & 63, oh = t >> 6;
    float acc[4] = {0.f, 0.f, 0.f, 0.f};
#pragma unroll
    for (int s = 0; s < 8; s++) {
        float xv = sxv[s * 64 + pl];
#pragma unroll
        for (int j = 0; j < 4; j++)
            acc[j] = fmaf(xv, spw[(oh * 4 + j) * 60 + s], acc[j]);
    }
    const float4* w4 = reinterpret_cast<const float4*>(sw + pl * KP);
#pragma unroll
    for (int k4 = 0; k4 < 13; k4++) {
        float4 wv = w4[k4];
#pragma unroll
        for (int j = 0; j < 4; j++) {
            float4 pv = *reinterpret_cast<const float4*>(spw + (oh * 4 + j) * 60 + 8 + k4 * 4);
            acc[j] = fmaf(wv.x, pv.x, acc[j]);
            acc[j] = fmaf(wv.y, pv.y, acc[j]);
            acc[j] = fmaf(wv.z, pv.z, acc[j]);
            acc[j] = fmaf(wv.w, pv.w, acc[j]);
        }
    }
#pragma unroll
    for (int j = 0; j < 4; j++)
        out[((size_t)b * OUT_ + g * 8 + oh * 4 + j) * HW + p0 + pl] = acc[j];
}

// ---------------- launch ---------------------------------------------------
extern "C" void kernel_launch(void* const* d_in, const int* in_sizes, int n_in,
                              void* d_out, int out_size) {
    const float* x    = (const float*)d_in[0];
    const float* w1   = (const float*)d_in[1];
    const float* b1   = (const float*)d_in[2];
    const float* w2   = (const float*)d_in[3];
    const float* b2   = (const float*)d_in[4];
    const float* w3   = (const float*)d_in[5];
    const float* b3   = (const float*)d_in[6];
    const float* bn1g = (const float*)d_in[7];
    const float* bn1b = (const float*)d_in[8];
    const float* bn1m = (const float*)d_in[9];
    const float* bn1v = (const float*)d_in[10];
    const float* cw1  = (const float*)d_in[11];
    const float* bn2g = (const float*)d_in[12];
    const float* bn2b = (const float*)d_in[13];
    const float* bn2m = (const float*)d_in[14];
    const float* bn2v = (const float*)d_in[15];
    const float* cw2  = (const float*)d_in[16];
    const float* cb   = (const float*)d_in[17];
    const float* p2w  = (const float*)d_in[18];
    float* out = (float*)d_out;

    cudaFuncSetAttribute(attn_kernel, cudaFuncAttributeMaxDynamicSharedMemorySize, ATT_SMEM);

    pack_kernel<<<(MPROJ * CIN + 255) / 256, 256>>>(w1, b1, w2, b2, w3, b3,
                                                    bn1g, bn1b, bn1m, bn1v, cw1, cw2);

    prep_x<<<dim3(HW / 32, CIN / 32, B_), 256>>>(x);

    proj_gemm<<<dim3(HW / 64, MPROJ / 96, B_), 256>>>();

    pad_kernel<<<dim3(PC_, B_), 256>>>();

    attn_kernel<<<dim3(HW / 8, B_), 384, ATT_SMEM>>>(bn2g, bn2b, bn2m, bn2v, cb);

    dim3 ga(49, WS_, B_);
    agg_kernel<<<ga, 128>>>();
    pos2_kernel<<<ga, 128>>>(p2w, out);
}

// round 17
// speedup vs baseline: 1.0505x; 1.0505x over previous
#include <cuda_runtime.h>
#include <cuda_fp16.h>
#include <cstdint>

// ---------------- problem constants ----------------
#define B_    4
#define CIN   256
#define H_    56
#define W_    56
#define HW    3136
#define OUT_  256
#define WS_   32
#define K2    49
#define KP    52
#define MPROJ 288
#define PC_   272
#define PH    62
#define PW    64

// attn dynamic smem layout (bytes) — R11 winner
#define ATT_U0     0
#define ATT_SLOG   26624
#define ATT_SX2    58624
#define ATT_CW1H   65792
#define ATT_CW2H   66304
#define ATT_SX1    67328
#define ATT_SCB    67840
#define ATT_S2S    67968
#define ATT_T2S    68032
#define ATT_SINV   68096
#define ATT_SMEM   69120

// ---------------- scratch (device globals) --------------------------------
__device__ float  g_bc[MPROJ];
__device__ float  g_s1[16], g_t1[16];
__device__ __align__(16) __half g_cw1h[256];
__device__ __align__(16) __half g_cw2h[512];
__device__ __align__(16) __half g_wch_b[MPROJ * CIN];
__device__ __align__(16) __half g_wch_s[MPROJ * CIN];
__device__ __align__(16) __half g_xtb[(size_t)B_ * HW * CIN];
__device__ __align__(16) __half g_xts[(size_t)B_ * HW * CIN];
__device__ float  g_proj[B_ * MPROJ * HW];
__device__ float  g_pad[(size_t)B_ * PC_ * PH * PW];
__device__ __half g_w[(size_t)B_ * WS_ * HW * KP];
__device__ float  g_agg[B_ * OUT_ * HW];

__device__ __forceinline__ int refl(int i, int n) {
    if (i < 0) i = -i;
    if (i >= n) i = 2 * n - 2 - i;
    return i;
}

__device__ __forceinline__ void mma16816(float (&d)[4], const unsigned (&a)[4],
                                         const unsigned (&b)[2], const float (&c)[4]) {
    asm volatile(
        "mma.sync.aligned.m16n8k16.row.col.f32.f16.f16.f32 "
        "{%0,%1,%2,%3}, {%4,%5,%6,%7}, {%8,%9}, {%10,%11,%12,%13};\n"
        : "=f"(d[0]), "=f"(d[1]), "=f"(d[2]), "=f"(d[3])
        : "r"(a[0]), "r"(a[1]), "r"(a[2]), "r"(a[3]),
          "r"(b[0]), "r"(b[1]),
          "f"(c[0]), "f"(c[1]), "f"(c[2]), "f"(c[3]));
}

__device__ __forceinline__ void ldmatrix_x4(unsigned (&r)[4], uint32_t addr) {
    asm volatile("ldmatrix.sync.aligned.m8n8.x4.shared.b16 {%0,%1,%2,%3}, [%4];\n"
                 : "=r"(r[0]), "=r"(r[1]), "=r"(r[2]), "=r"(r[3]) : "r"(addr));
}

__device__ __forceinline__ void ldmatrix_x2(unsigned (&r)[2], uint32_t addr) {
    asm volatile("ldmatrix.sync.aligned.m8n8.x2.shared.b16 {%0,%1}, [%2];\n"
                 : "=r"(r[0]), "=r"(r[1]) : "r"(addr));
}

// ---------------- kernel 0: pack weights + bn1 fold + fp16 splits ---------
__global__ void pack_kernel(const float* __restrict__ w1, const float* __restrict__ b1,
                            const float* __restrict__ w2, const float* __restrict__ b2,
                            const float* __restrict__ w3, const float* __restrict__ b3,
                            const float* __restrict__ bn1g, const float* __restrict__ bn1b,
                            const float* __restrict__ bn1m, const float* __restrict__ bn1v,
                            const float* __restrict__ cw1, const float* __restrict__ cw2) {
    int i = blockIdx.x * blockDim.x + threadIdx.x;
    if (i < MPROJ * CIN) {
        int r = i / CIN, c = i % CIN;
        float v;
        if (r < 16)      v = w1[r * CIN + c];
        else if (r < 32) v = w2[(r - 16) * CIN + c];
        else             v = w3[(r - 32) * CIN + c];
        __half hb = __float2half(v);
        g_wch_b[i] = hb;
        g_wch_s[i] = __float2half(v - __half2float(hb));
    }
    if (i < MPROJ) {
        g_bc[i] = (i < 16) ? b1[i] : ((i < 32) ? b2[i - 16] : b3[i - 32]);
    }
    if (i < 16) {
        float s = bn1g[i] * rsqrtf(bn1v[i] + 1e-5f);
        g_s1[i] = s;
        g_t1[i] = bn1b[i] - s * bn1m[i];
    }
    if (i < 256) g_cw1h[i] = __float2half(cw1[i]);
    if (i < 512) g_cw2h[i] = __float2half(cw2[i]);
}

// ---------------- kernel 0b: transpose + fp16-split X ---------------------
__global__ __launch_bounds__(256) void prep_x(const float* __restrict__ x) {
    __shared__ float tile[32][33];
    int p0 = blockIdx.x * 32, k0 = blockIdx.y * 32, b = blockIdx.z;
    int t = threadIdx.x;
    for (int i = t; i < 1024; i += 256) {
        int kk = i >> 5, pp = i & 31;
        tile[kk][pp] = x[((size_t)(b * CIN + k0 + kk)) * HW + p0 + pp];
    }
    __syncthreads();
    for (int i = t; i < 1024; i += 256) {
        int pp = i >> 5, kk = i & 31;
        float v = tile[kk][pp];
        __half hb = __float2half(v);
        size_t o = ((size_t)(b * HW + p0 + pp)) * CIN + k0 + kk;
        g_xtb[o] = hb;
        g_xts[o] = __float2half(v - __half2float(hb));
    }
}

// ---------------- kernel 1: projection GEMM via 3-term fp16 HMMA ----------
__global__ __launch_bounds__(256) void proj_gemm() {
    __shared__ __align__(16) __half Xb[64 * 72], Xs[64 * 72];
    __shared__ __align__(16) __half Wb[96 * 72], Ws[96 * 72];

    int b  = blockIdx.z;
    int p0 = blockIdx.x * 64;
    int ch0 = blockIdx.y * 96;
    int t  = threadIdx.x;
    int warp = t >> 5, lane = t & 31;
    int mt = warp >> 1, nh = warp & 1;
    int qp = lane & 3, rp = lane >> 2;

    float acc[6][4];
#pragma unroll
    for (int j = 0; j < 6; j++)
#pragma unroll
        for (int c = 0; c < 4; c++) acc[j][c] = 0.0f;

    uint32_t xb_base = (uint32_t)__cvta_generic_to_shared(Xb);
    uint32_t xs_base = (uint32_t)__cvta_generic_to_shared(Xs);
    uint32_t wb_base = (uint32_t)__cvta_generic_to_shared(Wb);
    uint32_t ws_base = (uint32_t)__cvta_generic_to_shared(Ws);
    uint32_t a_off = (uint32_t)(mt * 16 + (lane & 15)) * 144u + (uint32_t)(lane >> 4) * 16u;
    int ln = lane & 15;
    uint32_t b_lane_off = (uint32_t)(ln & 7) * 144u + ((ln & 8) ? 16u : 0u);

    const uint4* gxb4 = reinterpret_cast<const uint4*>(g_xtb);
    const uint4* gxs4 = reinterpret_cast<const uint4*>(g_xts);
    const uint4* gwb4 = reinterpret_cast<const uint4*>(g_wch_b);
    const uint4* gws4 = reinterpret_cast<const uint4*>(g_wch_s);

    for (int k0 = 0; k0 < CIN; k0 += 64) {
        int kq = k0 >> 3;
        for (int i = t; i < 512; i += 256) {
            int r = i >> 3, c = i & 7;
            size_t src = (size_t)(b * HW + p0 + r) * 32 + kq + c;
            reinterpret_cast<uint4*>(Xb)[r * 9 + c] = gxb4[src];
            reinterpret_cast<uint4*>(Xs)[r * 9 + c] = gxs4[src];
        }
        for (int i = t; i < 768; i += 256) {
            int r = i >> 3, c = i & 7;
            size_t src = (size_t)(ch0 + r) * 32 + kq + c;
            reinterpret_cast<uint4*>(Wb)[r * 9 + c] = gwb4[src];
            reinterpret_cast<uint4*>(Ws)[r * 9 + c] = gws4[src];
        }
        __syncthreads();

#pragma unroll
        for (int kk = 0; kk < 4; kk++) {
            unsigned axb[4], axs[4];
            ldmatrix_x4(axb, xb_base + a_off + (uint32_t)kk * 32u);
            ldmatrix_x4(axs, xs_base + a_off + (uint32_t)kk * 32u);
#pragma unroll
            for (int j = 0; j < 6; j++) {
                uint32_t boff = (uint32_t)((nh * 6 + j) * 1152) + b_lane_off
                              + (uint32_t)kk * 32u;
                unsigned bb[2], bs[2];
                ldmatrix_x2(bb, wb_base + boff);
                ldmatrix_x2(bs, ws_base + boff);
                mma16816(acc[j], axb, bb, acc[j]);
                mma16816(acc[j], axs, bb, acc[j]);
                mma16816(acc[j], axb, bs, acc[j]);
            }
        }
        __syncthreads();
    }

    int pxl = p0 + mt * 16 + rp;
#pragma unroll
    for (int j = 0; j < 6; j++) {
        int chg = ch0 + (nh * 6 + j) * 8 + 2 * qp;
        float b0 = g_bc[chg], b1 = g_bc[chg + 1];
        float v0 = acc[j][0] + b0, v1 = acc[j][1] + b1;
        float v2 = acc[j][2] + b0, v3 = acc[j][3] + b1;
        if (chg < 16)      { float s = g_s1[chg], tt = g_t1[chg];
                             v0 = fmaf(s, v0, tt); v2 = fmaf(s, v2, tt); }
        else if (chg < 32) { float s = g_s1[chg - 16]; v0 *= s; v2 *= s; }
        int ch1 = chg + 1;
        if (ch1 < 16)      { float s = g_s1[ch1], tt = g_t1[ch1];
                             v1 = fmaf(s, v1, tt); v3 = fmaf(s, v3, tt); }
        else if (ch1 < 32) { float s = g_s1[ch1 - 16]; v1 *= s; v3 *= s; }
        size_t r0 = (size_t)(b * MPROJ + chg) * HW;
        size_t r1 = (size_t)(b * MPROJ + ch1) * HW;
        g_proj[r0 + pxl]     = v0;
        g_proj[r1 + pxl]     = v1;
        g_proj[r0 + pxl + 8] = v2;
        g_proj[r1 + pxl + 8] = v3;
    }
}

// ---------------- kernel 1b: reflect-pad (batched loads, MLP=16) ----------
__global__ __launch_bounds__(256) void pad_kernel() {
    int c = blockIdx.x, b = blockIdx.y;
    const float* src = g_proj + ((size_t)(b * MPROJ + 16 + c)) * HW;
    float* dst = g_pad + ((size_t)(b * PC_ + c)) * PH * PW;
    int t = threadIdx.x;
    int col = t & 63;
    int r0 = t >> 6;
    int ox = refl(col - 3, W_);
    float v[16];
#pragma unroll
    for (int i = 0; i < 16; i++) {
        int r = r0 + i * 4;
        if (r < PH) {
            int oy = refl(r - 3, H_);
            v[i] = src[oy * W_ + ox];
        }
    }
#pragma unroll
    for (int i = 0; i < 16; i++) {
        int r = r0 + i * 4;
        if (r < PH) dst[r * PW + col] = v[i];
    }
}

// ---------------- kernel 2: attention weights + softmax (R11 HMMA) --------
__global__ __launch_bounds__(384, 3) void attn_kernel(
    const float* __restrict__ bn2g, const float* __restrict__ bn2b,
    const float* __restrict__ bn2m, const float* __restrict__ bn2v,
    const float* __restrict__ cb) {

    extern __shared__ __align__(16) char smem_raw[];
    __half* act0h = (__half*)(smem_raw + ATT_U0);
    __half* slog2 = (__half*)(smem_raw + ATT_U0);
    __half* slog  = (__half*)(smem_raw + ATT_SLOG);
    float*  sx2   = (float*)(smem_raw + ATT_SX2);
    __half* scw1h = (__half*)(smem_raw + ATT_CW1H);
    __half* scw2h = (__half*)(smem_raw + ATT_CW2H);
    float*  sx1   = (float*)(smem_raw + ATT_SX1);
    float*  scb   = (float*)(smem_raw + ATT_SCB);
    float*  s2s   = (float*)(smem_raw + ATT_S2S);
    float*  t2s   = (float*)(smem_raw + ATT_T2S);
    float*  sinv  = (float*)(smem_raw + ATT_SINV);

    int t = threadIdx.x;
    int b = blockIdx.y;
    int p0 = blockIdx.x * 8;
    int h = p0 / W_, w0 = p0 % W_;

    if (t < 32) {
        reinterpret_cast<uint4*>(scw1h)[t] = reinterpret_cast<const uint4*>(g_cw1h)[t];
    } else if (t < 96) {
        reinterpret_cast<uint4*>(scw2h)[t - 32] = reinterpret_cast<const uint4*>(g_cw2h)[t - 32];
    } else if (t < 128) {
        scb[t - 96] = cb[t - 96];
    } else if (t < 144) {
        int c = t - 128;
        float ss = bn2g[c] * rsqrtf(bn2v[c] + 1e-5f);
        s2s[c] = ss; t2s[c] = bn2b[c] - ss * bn2m[c];
    } else if (t < 272) {
        int idx = t - 144;
        int c = idx >> 3, pix = idx & 7;
        sx1[pix * 16 + c] = g_proj[((size_t)b * MPROJ + c) * HW + p0 + pix];
    }
    const float* padb = g_pad + (size_t)b * PC_ * PH * PW;
    for (int i = t; i < 448; i += 384) {
        int c = i / 28, rem = i - c * 28, dy = rem >> 2, cg = rem & 3;
        float4 v = *reinterpret_cast<const float4*>(
            padb + ((size_t)c * PH + h + dy) * PW + w0 + cg * 4);
        *reinterpret_cast<float4*>(sx2 + c * 112 + dy * 16 + cg * 4) = v;
    }
    __syncthreads();

    for (int pt = t; pt < 392; pt += 384) {
        int pix = pt & 7, k = pt >> 3;
        int dy = k / 7, dx = k - dy * 7;
        const float* x2p = sx2 + dy * 16 + dx + pix;
        const float* x1p = sx1 + pix * 16;
        __half2* dst = reinterpret_cast<__half2*>(act0h + pt * 24);
#pragma unroll
        for (int q = 0; q < 8; q++) {
            float a0 = fmaxf(x1p[2 * q]     - x2p[(2 * q) * 112],     0.0f);
            float a1 = fmaxf(x1p[2 * q + 1] - x2p[(2 * q + 1) * 112], 0.0f);
            dst[q] = __floats2half2_rn(a0, a1);
        }
    }
    __syncthreads();

    {
        int warp = t >> 5, lane = t & 31;
        int qp = lane & 3, rp = lane >> 2;
        int k0 = qp * 2;

        unsigned b1f[2][2], b2f[4][2];
#pragma unroll
        for (int j = 0; j < 2; j++) {
            int o = j * 8 + rp;
            b1f[j][0] = *reinterpret_cast<const unsigned*>(scw1h + o * 16 + k0);
            b1f[j][1] = *reinterpret_cast<const unsigned*>(scw1h + o * 16 + k0 + 8);
        }
#pragma unroll
        for (int j = 0; j < 4; j++) {
            int g = j * 8 + rp;
            b2f[j][0] = *reinterpret_cast<const unsigned*>(scw2h + g * 16 + k0);
            b2f[j][1] = *reinterpret_cast<const unsigned*>(scw2h + g * 16 + k0 + 8);
        }
        float s2v[4] = {s2s[k0], s2s[k0 + 1], s2s[k0 + 8], s2s[k0 + 9]};
        float t2v[4] = {t2s[k0], t2s[k0 + 1], t2s[k0 + 8], t2s[k0 + 9]};
        float cbv[4][2];
#pragma unroll
        for (int j = 0; j < 4; j++) {
            cbv[j][0] = scb[j * 8 + k0];
            cbv[j][1] = scb[j * 8 + k0 + 1];
        }

        uint32_t act_base = (uint32_t)__cvta_generic_to_shared(act0h);
        for (int tile = warp; tile < 25; tile += 12) {
            unsigned a1[4];
            uint32_t addr = act_base + (uint32_t)(tile * 16 + (lane & 15)) * 48u
                          + (uint32_t)(lane >> 4) * 16u;
            ldmatrix_x4(a1, addr);

            float z4[4] = {0.f, 0.f, 0.f, 0.f};
            float d0[4], d1[4];
            mma16816(d0, a1, b1f[0], z4);
            mma16816(d1, a1, b1f[1], z4);

            unsigned a2[4];
            {
                __half2 hv;
                hv = __floats2half2_rn(fmaxf(fmaf(s2v[0], d0[0], t2v[0]), 0.f),
                                       fmaxf(fmaf(s2v[1], d0[1], t2v[1]), 0.f));
                a2[0] = *reinterpret_cast<unsigned*>(&hv);
                hv = __floats2half2_rn(fmaxf(fmaf(s2v[0], d0[2], t2v[0]), 0.f),
                                       fmaxf(fmaf(s2v[1], d0[3], t2v[1]), 0.f));
                a2[1] = *reinterpret_cast<unsigned*>(&hv);
                hv = __floats2half2_rn(fmaxf(fmaf(s2v[2], d1[0], t2v[2]), 0.f),
                                       fmaxf(fmaf(s2v[3], d1[1], t2v[3]), 0.f));
                a2[2] = *reinterpret_cast<unsigned*>(&hv);
                hv = __floats2half2_rn(fmaxf(fmaf(s2v[2], d1[2], t2v[2]), 0.f),
                                       fmaxf(fmaf(s2v[3], d1[3], t2v[3]), 0.f));
                a2[3] = *reinterpret_cast<unsigned*>(&hv);
            }

            int r0 = tile * 16 + rp;
            bool hi_ok = (r0 + 8 < 392);
#pragma unroll
            for (int j = 0; j < 4; j++) {
                float c2[4] = {cbv[j][0], cbv[j][1], cbv[j][0], cbv[j][1]};
                mma16816(c2, a2, b2f[j], c2);
                int g0 = j * 8 + k0;
                *reinterpret_cast<__half2*>(slog + r0 * 40 + g0) =
                    __floats2half2_rn(c2[0], c2[1]);
                if (hi_ok)
                    *reinterpret_cast<__half2*>(slog + (r0 + 8) * 40 + g0) =
                        __floats2half2_rn(c2[2], c2[3]);
            }
        }
    }
    __syncthreads();

    if (t < 256) {
        int pix = t >> 5, g = t & 31;
        const __half* src = slog + pix * 40 + g;
        float m = -1e30f;
#pragma unroll
        for (int k = 0; k < 49; k++) m = fmaxf(m, __half2float(src[k * 320]));
        __half* dst = slog2 + (pix * 32 + g) * 52;
        float s = 0.0f;
#pragma unroll
        for (int k = 0; k < 49; k++) {
            float e = __expf(__half2float(src[k * 320]) - m);
            s += e;
            dst[k] = __float2half(e);
        }
        dst[49] = __float2half(0.0f);
        dst[50] = __float2half(0.0f);
        dst[51] = __float2half(0.0f);
        sinv[t] = 1.0f / s;
    }
    __syncthreads();

    {
        __half2* gw2 = reinterpret_cast<__half2*>(g_w);
        const __half2* sl2 = reinterpret_cast<const __half2*>(slog2);
        int r = t / 26, k2 = t - r * 26;
        for (int i = t; i < 6656; i += 384) {
            int pix = r >> 5, g = r & 31;
            float2 f = __half22float2(sl2[r * 26 + k2]);
            float inv = sinv[r];
            gw2[(((size_t)(b * WS_ + g)) * HW + p0 + pix) * 26 + k2] =
                __floats2half2_rn(f.x * inv, f.y * inv);
            r += 14; k2 += 20;
            if (k2 >= 26) { k2 -= 26; r++; }
        }
    }
}

// ---------------- kernel 3: aggregation (R12 version) ---------------------
__global__ __launch_bounds__(128) void agg_kernel() {
    __shared__ __align__(4) __half swh[64 * KP];
    __shared__ __align__(16) float sx3[8 * 14 * 24];

    int b = blockIdx.z, g = blockIdx.y, tile = blockIdx.x;
    int ty0 = (tile / 7) * 8, tx0 = (tile % 7) * 8;
    int t = threadIdx.x;

    const __half2* gw2 = reinterpret_cast<const __half2*>(g_w);
    size_t wbase = ((size_t)(b * WS_ + g)) * HW;
    for (int i = t; i < 1664; i += 128) {
        int run = i / 208, off = i - run * 208;
        reinterpret_cast<__half2*>(swh)[run * 208 + off] =
            gw2[(wbase + (ty0 + run) * W_ + tx0) * 26 + off];
    }
    const float* padb = g_pad + ((size_t)(b * PC_) + 16 + g * 8) * PH * PW;
    for (int i = t; i < 448; i += 128) {
        int c = i / 56, rem = i - c * 56, r = rem >> 2, cg = rem & 3;
        float4 v = *reinterpret_cast<const float4*>(
            padb + ((size_t)c * PH + ty0 + r) * PW + tx0 + cg * 4);
        *reinterpret_cast<float4*>(sx3 + (c * 14 + r) * 24 + cg * 4) = v;
    }
    __syncthreads();

    int pl = t & 63, sq = t >> 6;
    int pr = pl >> 3, pc = pl & 7;
    const __half2* wp = reinterpret_cast<const __half2*>(swh + pl * KP);
    const float* xb = sx3 + sq * 4 * 336 + pr * 24 + pc;

    float a0 = 0.f, a1 = 0.f, a2 = 0.f, a3 = 0.f;
#pragma unroll
    for (int k2 = 0; k2 < 25; k2++) {
        float2 wf = __half22float2(wp[k2]);
        {
            int k = 2 * k2;
            int xo = (k / 7) * 24 + (k % 7);
            a0 = fmaf(xb[xo],        wf.x, a0);
            a1 = fmaf(xb[336 + xo],  wf.x, a1);
            a2 = fmaf(xb[672 + xo],  wf.x, a2);
            a3 = fmaf(xb[1008 + xo], wf.x, a3);
        }
        if (2 * k2 + 1 < 49) {
            int k = 2 * k2 + 1;
            int xo = (k / 7) * 24 + (k % 7);
            a0 = fmaf(xb[xo],        wf.y, a0);
            a1 = fmaf(xb[336 + xo],  wf.y, a1);
            a2 = fmaf(xb[672 + xo],  wf.y, a2);
            a3 = fmaf(xb[1008 + xo], wf.y, a3);
        }
    }
    int p = (ty0 + pr) * W_ + tx0 + pc;
    float* dst = g_agg + ((size_t)b * OUT_ + g * 8 + sq * 4) * HW + p;
    dst[0] = a0; dst[HW] = a1; dst[2 * HW] = a2; dst[3 * HW] = a3;
}

// ---------------- kernel 4: position2 grouped conv ------------------------
__global__ __launch_bounds__(128) void pos2_kernel(const float* __restrict__ pos2w,
                                                   float* __restrict__ out) {
    __shared__ __align__(16) float sw[64 * KP];
    __shared__ __align__(16) float spw[8 * 60];
    __shared__ float sxv[8 * 64];

    int b = blockIdx.z, g = blockIdx.y, p0 = blockIdx.x * 64;
    int t = threadIdx.x;

    const __half2* gw2 = reinterpret_cast<const __half2*>(g_w);
    size_t base2 = (((size_t)(b * WS_ + g)) * HW + p0) * 26;
    for (int i = t; i < 1664; i += 128) {
        float2 f = __half22float2(gw2[base2 + i]);
        *reinterpret_cast<float2*>(sw + 2 * i) = f;
    }
    for (int i = t; i < 480; i += 128) {
        int o = i / 60, q = i - o * 60;
        spw[i] = (q < 57) ? pos2w[(g * 8 + o) * 57 + q] : 0.0f;
    }
    for (int i = t; i < 512; i += 128) {
        int s = i >> 6, pl = i & 63;
        sxv[i] = g_agg[((size_t)b * OUT_ + s * 32 + g) * HW + p0 + pl];
    }
    __syncthreads();

    int pl = t & 63, oh = t >> 6;
    float acc[4] = {0.f, 0.f, 0.f, 0.f};
#pragma unroll
    for (int s = 0; s < 8; s++) {
        float xv = sxv[s * 64 + pl];
#pragma unroll
        for (int j = 0; j < 4; j++)
            acc[j] = fmaf(xv, spw[(oh * 4 + j) * 60 + s], acc[j]);
    }
    const float4* w4 = reinterpret_cast<const float4*>(sw + pl * KP);
#pragma unroll
    for (int k4 = 0; k4 < 13; k4++) {
        float4 wv = w4[k4];
#pragma unroll
        for (int j = 0; j < 4; j++) {
            float4 pv = *reinterpret_cast<const float4*>(spw + (oh * 4 + j) * 60 + 8 + k4 * 4);
            acc[j] = fmaf(wv.x, pv.x, acc[j]);
            acc[j] = fmaf(wv.y, pv.y, acc[j]);
            acc[j] = fmaf(wv.z, pv.z, acc[j]);
            acc[j] = fmaf(wv.w, pv.w, acc[j]);
        }
    }
#pragma unroll
    for (int j = 0; j < 4; j++)
        out[((size_t)b * OUT_ + g * 8 + oh * 4 + j) * HW + p0 + pl] = acc[j];
}

// ---------------- launch ---------------------------------------------------
extern "C" void kernel_launch(void* const* d_in, const int* in_sizes, int n_in,
                              void* d_out, int out_size) {
    const float* x    = (const float*)d_in[0];
    const float* w1   = (const float*)d_in[1];
    const float* b1   = (const float*)d_in[2];
    const float* w2   = (const float*)d_in[3];
    const float* b2   = (const float*)d_in[4];
    const float* w3   = (const float*)d_in[5];
    const float* b3   = (const float*)d_in[6];
    const float* bn1g = (const float*)d_in[7];
    const float* bn1b = (const float*)d_in[8];
    const float* bn1m = (const float*)d_in[9];
    const float* bn1v = (const float*)d_in[10];
    const float* cw1  = (const float*)d_in[11];
    const float* bn2g = (const float*)d_in[12];
    const float* bn2b = (const float*)d_in[13];
    const float* bn2m = (const float*)d_in[14];
    const float* bn2v = (const float*)d_in[15];
    const float* cw2  = (const float*)d_in[16];
    const float* cb   = (const float*)d_in[17];
    const float* p2w  = (const float*)d_in[18];
    float* out = (float*)d_out;

    cudaFuncSetAttribute(attn_kernel, cudaFuncAttributeMaxDynamicSharedMemorySize, ATT_SMEM);

    pack_kernel<<<(MPROJ * CIN + 255) / 256, 256>>>(w1, b1, w2, b2, w3, b3,
                                                    bn1g, bn1b, bn1m, bn1v, cw1, cw2);

    prep_x<<<dim3(HW / 32, CIN / 32, B_), 256>>>(x);

    proj_gemm<<<dim3(HW / 64, MPROJ / 96, B_), 256>>>();

    pad_kernel<<<dim3(PC_, B_), 256>>>();

    attn_kernel<<<dim3(HW / 8, B_), 384, ATT_SMEM>>>(bn2g, bn2b, bn2m, bn2v, cb);

    dim3 ga(49, WS_, B_);
    agg_kernel<<<ga, 128>>>();
    pos2_kernel<<<ga, 128>>>(p2w, out);
}